// round 16
// baseline (speedup 1.0000x reference)
#include <cuda_runtime.h>

// SSIM loss, fused separable. R11 makespan-balanced grid (6 strips/image:
// 5x TH=89 + 1x TH=67, NITER multiples of 11 -> ring slots constant-fold)
// + packed f32x2 math body (FFMA2: 2 FMAs per issue slot) now that the
// kernel is issue-slot bound (issue=78%).
// pred, gt: f32 [16,3,512,512] -> out: f32 scalar = 1 - mean(ssim_map)

#define IMG_H 512
#define IMG_W 512
#define N_IMG 48
#define NSTRIP 6
#define NBLK (N_IMG * NSTRIP)     // 288
#define SPAD 8
#define SW (IMG_W + 2 * SPAD)     // 528
#define C1F 0.0001f
#define C2F 0.0009f

#define GW0 0.00102838f
#define GW1 0.00759876f
#define GW2 0.03600078f
#define GW3 0.10936069f
#define GW4 0.21300553f
#define GW5 0.26601172f

__device__ float        g_partials[NBLK];
__device__ unsigned int g_count;          // zero-init; last block re-arms

typedef unsigned long long u64;

static __device__ __forceinline__ u64 pack2(float lo, float hi) {
    u64 r; asm("mov.b64 %0, {%1, %2};" : "=l"(r) : "f"(lo), "f"(hi)); return r;
}
static __device__ __forceinline__ void unpack2(u64 v, float& lo, float& hi) {
    asm("mov.b64 {%0, %1}, %2;" : "=f"(lo), "=f"(hi) : "l"(v));
}
static __device__ __forceinline__ u64 fma2(u64 a, u64 b, u64 c) {
    u64 d; asm("fma.rn.f32x2 %0, %1, %2, %3;" : "=l"(d) : "l"(a), "l"(b), "l"(c)); return d;
}
static __device__ __forceinline__ u64 mul2(u64 a, u64 b) {
    u64 d; asm("mul.rn.f32x2 %0, %1, %2;" : "=l"(d) : "l"(a), "l"(b)); return d;
}

// One strip: THT output rows, NITERT = THT+10 input rows, NITERT % 11 == 0.
template<int THT, int NITERT>
static __device__ __forceinline__
float strip_body(const float* __restrict__ px, const float* __restrict__ py,
                 const int row0, const int c, u64 (&s2)[2][SW],
                 const u64 (&W2)[6], const float (&Wt)[6])
{
    // vertical ring: packed (mu1,mu2), packed (Exx,Eyy), scalar Exy
    u64 amu[11], avar[11]; float axy[11];
    #pragma unroll
    for (int j = 0; j < 11; ++j) { amu[j] = 0ULL; avar[j] = 0ULL; axy[j] = 0.f; }

    // preload input row 0 (global row row0-5)
    float xc = 0.f, yc = 0.f;
    {
        const int gr = row0 - 5;
        if ((unsigned)gr < IMG_H) { xc = px[gr * IMG_W + c]; yc = py[gr * IMG_W + c]; }
    }

    float tsum = 0.f;

    #pragma unroll 1
    for (int rb = 0; rb < NITERT; rb += 11) {
        #pragma unroll
        for (int i = 0; i < 11; ++i) {        // rb%11==0 -> ring slots fold
            const int r = rb + i;
            const int b = r & 1;

            s2[b][SPAD + c] = pack2(xc, yc);
            __syncthreads();

            // prefetch next row under this row's compute
            float xn = 0.f, yn = 0.f;
            {
                const int gr = row0 - 5 + r + 1;
                if ((r + 1 < NITERT) && ((unsigned)gr < IMG_H)) {
                    xn = px[gr * IMG_W + c];
                    yn = py[gr * IMG_W + c];
                }
            }

            // horizontal 11-tap conv: packed mu / packed var, scalar xy
            u64 hmu = 0ULL, hvar = 0ULL; float hxy = 0.f;
            #pragma unroll
            for (int k = 0; k < 11; ++k) {
                const int wi = (k < 6) ? k : 10 - k;
                const u64 P  = s2[b][SPAD - 5 + c + k];   // LDS.64 (x,y)
                hmu  = fma2(P, W2[wi], hmu);
                const u64 PP = mul2(P, P);                // (x*x, y*y), 1 slot
                hvar = fma2(PP, W2[wi], hvar);
                float pl, ph; unpack2(P, pl, ph);         // reg aliases, free
                hxy  = fmaf(pl * ph, Wt[wi], hxy);        // FMUL + FFMA-imm
            }

            // vertical scatter into ring (slot indices constant-folded)
            #pragma unroll
            for (int j = 0; j < 11; ++j) {
                const int s  = (i + 1 + j) % 11;
                const int wi = (j < 6) ? j : 10 - j;
                amu[s]  = fma2(hmu,  W2[wi], amu[s]);
                avar[s] = fma2(hvar, W2[wi], avar[s]);
                axy[s]  = fmaf(hxy, Wt[wi], axy[s]);      // FFMA-imm
            }

            // slot (i+1)%11 completed -> output row r-10
            const int s0 = (i + 1) % 11;
            const int o  = r - 10;
            if (o >= 0 && o < THT) {
                float mu1, mu2, Exx, Eyy;
                unpack2(amu[s0], mu1, mu2);
                unpack2(avar[s0], Exx, Eyy);
                const float m11 = mu1 * mu1;
                const float m22 = mu2 * mu2;
                const float m12 = mu1 * mu2;
                const float v1  = Exx - m11;
                const float v2  = Eyy - m22;
                const float v12 = axy[s0] - m12;
                const float num = (2.f * m12 + C1F) * (2.f * v12 + C2F);
                const float den = (m11 + m22 + C1F) * (v1 + v2 + C2F);
                tsum += __fdividef(num, den);
            }
            amu[s0] = 0ULL; avar[s0] = 0ULL; axy[s0] = 0.f;

            xc = xn; yc = yn;
        }
    }
    return tsum;
}

__global__ __launch_bounds__(512, 1)
void ssim_main(const float* __restrict__ pred, const float* __restrict__ gt,
               float* __restrict__ out)
{
    __shared__ u64   s2[2][SW];            // packed (x,y) rows, double buffered
    __shared__ float sred[16];
    __shared__ unsigned int s_last;

    const float Wt[6] = {GW0, GW1, GW2, GW3, GW4, GW5};
    u64 W2[6];
    #pragma unroll
    for (int i = 0; i < 6; ++i) W2[i] = pack2(Wt[i], Wt[i]);

    const int c     = threadIdx.x;         // one thread per column
    const int strip = blockIdx.x;          // 0..5
    const int img   = blockIdx.y;
    const int bid   = img * NSTRIP + strip;
    const float* px = pred + (size_t)img * (IMG_H * IMG_W);
    const float* py = gt   + (size_t)img * (IMG_H * IMG_W);

    // zero column halos (stay zero; first-iteration barrier orders them)
    if (c < SPAD) {
        s2[0][c] = 0ULL; s2[1][c] = 0ULL;
        s2[0][SPAD + IMG_W + c] = 0ULL; s2[1][SPAD + IMG_W + c] = 0ULL;
    }

    float tsum;
    if (strip < 5) tsum = strip_body<89, 99>(px, py, strip * 89, c, s2, W2, Wt);
    else           tsum = strip_body<67, 77>(px, py, 445,        c, s2, W2, Wt);

    // deterministic block reduction
    #pragma unroll
    for (int off = 16; off > 0; off >>= 1)
        tsum += __shfl_down_sync(0xffffffffu, tsum, off);
    if ((c & 31) == 0) sred[c >> 5] = tsum;
    __syncthreads();
    if (c == 0) {
        float s = 0.f;
        #pragma unroll
        for (int w = 0; w < 16; ++w) s += sred[w];
        g_partials[bid] = s;
        __threadfence();
        const unsigned int old = atomicAdd(&g_count, 1u);
        s_last = (old == NBLK - 1) ? 1u : 0u;
    }
    __syncthreads();

    // last-finishing block reduces the 288 partials (fixed order, deterministic)
    if (s_last) {
        float v = (c < NBLK) ? __ldcg(&g_partials[c]) : 0.f;
        #pragma unroll
        for (int off = 16; off > 0; off >>= 1)
            v += __shfl_down_sync(0xffffffffu, v, off);
        if ((c & 31) == 0) sred[c >> 5] = v;
        __syncthreads();
        if (c == 0) {
            float s = 0.f;
            #pragma unroll
            for (int w = 0; w < 16; ++w) s += sred[w];
            out[0] = 1.0f - s * (1.0f / 12582912.0f);
            g_count = 0;                   // re-arm for next graph replay
        }
    }
}

extern "C" void kernel_launch(void* const* d_in, const int* in_sizes, int n_in,
                              void* d_out, int out_size)
{
    (void)in_sizes; (void)n_in; (void)out_size;
    const float* pred = (const float*)d_in[0];
    const float* gt   = (const float*)d_in[1];

    dim3 grid(NSTRIP, N_IMG);              // (6, 48) = 288 blocks, 2 waves
    ssim_main<<<grid, IMG_W>>>(pred, gt, (float*)d_out);
}

// round 17
// speedup vs baseline: 1.1416x; 1.1416x over previous
#include <cuda_runtime.h>

// SSIM loss, fused separable, 4-channel rotated basis.
// u = x+y, v = x-y  =>  conv channels (u, v, u^2, v^2) suffice:
//   mu1*mu2       = (U^2 - V^2)/4        mu1^2+mu2^2 = (U^2 + V^2)/2
//   E[x^2]+E[y^2] = (P + Q)/2            E[xy]       = (P - Q)/4
// which is exactly what the SSIM map needs -> 20% fewer conv ops than the
// 5-channel form. Scalar FFMA-imm body (rt=1) on the makespan-balanced grid
// (5x TH=89 + 1x TH=67 strips; NITER multiples of 11 so ring slots fold).
// pred, gt: f32 [16,3,512,512] -> out: f32 scalar = 1 - mean(ssim_map)

#define IMG_H 512
#define IMG_W 512
#define N_IMG 48
#define NSTRIP 6
#define NBLK (N_IMG * NSTRIP)     // 288
#define SPAD 8
#define SW (IMG_W + 2 * SPAD)     // 528
#define C1F 0.0001f
#define C2F 0.0009f

#define GW0 0.00102838f
#define GW1 0.00759876f
#define GW2 0.03600078f
#define GW3 0.10936069f
#define GW4 0.21300553f
#define GW5 0.26601172f

__device__ float        g_partials[NBLK];
__device__ unsigned int g_count;          // zero-init; last block re-arms

// One strip: THT output rows, NITERT = THT+10 input rows, NITERT % 11 == 0.
template<int THT, int NITERT>
static __device__ __forceinline__
float strip_body(const float* __restrict__ px, const float* __restrict__ py,
                 const int row0, const int c, float2 (&s2)[2][SW])
{
    const float Wt[11] = {GW0, GW1, GW2, GW3, GW4, GW5, GW4, GW3, GW2, GW1, GW0};

    // vertical ring: 4 channels x 11 slots, all registers
    float aU[11], aV[11], aP[11], aQ[11];
    #pragma unroll
    for (int j = 0; j < 11; ++j) { aU[j]=0.f; aV[j]=0.f; aP[j]=0.f; aQ[j]=0.f; }

    // preload input row 0 (global row row0-5), rotated basis
    float uc = 0.f, vc = 0.f;
    {
        const int gr = row0 - 5;
        if ((unsigned)gr < IMG_H) {
            const float x = px[gr * IMG_W + c];
            const float y = py[gr * IMG_W + c];
            uc = x + y; vc = x - y;
        }
    }

    float tsum = 0.f;

    #pragma unroll 1
    for (int rb = 0; rb < NITERT; rb += 11) {
        #pragma unroll
        for (int i = 0; i < 11; ++i) {        // rb%11==0 -> ring slots fold
            const int r = rb + i;
            const int b = r & 1;

            s2[b][SPAD + c] = make_float2(uc, vc);
            __syncthreads();

            // prefetch next row under this row's compute
            float un = 0.f, vn = 0.f;
            {
                const int gr = row0 - 5 + r + 1;
                if ((r + 1 < NITERT) && ((unsigned)gr < IMG_H)) {
                    const float x = px[gr * IMG_W + c];
                    const float y = py[gr * IMG_W + c];
                    un = x + y; vn = x - y;
                }
            }

            // horizontal 11-tap conv of 4 channels (weights -> FFMA-imm)
            float hU = 0.f, hV = 0.f, hP = 0.f, hQ = 0.f;
            #pragma unroll
            for (int k = 0; k < 11; ++k) {
                const float2 p = s2[b][SPAD - 5 + c + k];   // LDS.64 (u,v)
                hU = fmaf(p.x,       Wt[k], hU);
                hV = fmaf(p.y,       Wt[k], hV);
                hP = fmaf(p.x * p.x, Wt[k], hP);
                hQ = fmaf(p.y * p.y, Wt[k], hQ);
            }

            // vertical scatter into ring (slot indices constant-folded)
            #pragma unroll
            for (int j = 0; j < 11; ++j) {
                const int   s  = (i + 1 + j) % 11;
                const float wv = Wt[10 - j];                // literal -> imm
                aU[s] = fmaf(hU, wv, aU[s]);
                aV[s] = fmaf(hV, wv, aV[s]);
                aP[s] = fmaf(hP, wv, aP[s]);
                aQ[s] = fmaf(hQ, wv, aQ[s]);
            }

            // slot (i+1)%11 completed -> output row r-10
            const int s0 = (i + 1) % 11;
            const int o  = r - 10;
            if (o >= 0 && o < THT) {
                const float U = aU[s0], V = aV[s0];
                const float P = aP[s0], Q = aQ[s0];
                const float U2 = U * U, V2 = V * V;
                const float m12  = 0.25f * (U2 - V2);   // mu1*mu2
                const float msum = 0.5f  * (U2 + V2);   // mu1^2+mu2^2
                const float Exy  = 0.25f * (P - Q);     // E[xy]
                const float Esum = 0.5f  * (P + Q);     // E[x^2]+E[y^2]
                const float vsum = Esum - msum;         // sig1^2+sig2^2
                const float v12  = Exy - m12;           // sig12
                const float num  = (2.f * m12 + C1F) * (2.f * v12 + C2F);
                const float den  = (msum + C1F) * (vsum + C2F);
                tsum += __fdividef(num, den);
            }
            aU[s0] = 0.f; aV[s0] = 0.f; aP[s0] = 0.f; aQ[s0] = 0.f;

            uc = un; vc = vn;
        }
    }
    return tsum;
}

__global__ __launch_bounds__(512, 1)
void ssim_main(const float* __restrict__ pred, const float* __restrict__ gt,
               float* __restrict__ out)
{
    __shared__ float2 s2[2][SW];           // packed (u,v) rows, double buffered
    __shared__ float  sred[16];
    __shared__ unsigned int s_last;

    const int c     = threadIdx.x;         // one thread per column
    const int strip = blockIdx.x;          // 0..5
    const int img   = blockIdx.y;
    const int bid   = img * NSTRIP + strip;
    const float* px = pred + (size_t)img * (IMG_H * IMG_W);
    const float* py = gt   + (size_t)img * (IMG_H * IMG_W);

    // zero column halos (stay zero; first-iteration barrier orders them)
    if (c < SPAD) {
        const float2 z = make_float2(0.f, 0.f);
        s2[0][c] = z; s2[1][c] = z;
        s2[0][SPAD + IMG_W + c] = z; s2[1][SPAD + IMG_W + c] = z;
    }

    float tsum;
    if (strip < 5) tsum = strip_body<89, 99>(px, py, strip * 89, c, s2);
    else           tsum = strip_body<67, 77>(px, py, 445,        c, s2);

    // deterministic block reduction
    #pragma unroll
    for (int off = 16; off > 0; off >>= 1)
        tsum += __shfl_down_sync(0xffffffffu, tsum, off);
    if ((c & 31) == 0) sred[c >> 5] = tsum;
    __syncthreads();
    if (c == 0) {
        float s = 0.f;
        #pragma unroll
        for (int w = 0; w < 16; ++w) s += sred[w];
        g_partials[bid] = s;
        __threadfence();
        const unsigned int old = atomicAdd(&g_count, 1u);
        s_last = (old == NBLK - 1) ? 1u : 0u;
    }
    __syncthreads();

    // last-finishing block reduces the 288 partials (fixed order, deterministic)
    if (s_last) {
        float v = (c < NBLK) ? __ldcg(&g_partials[c]) : 0.f;
        #pragma unroll
        for (int off = 16; off > 0; off >>= 1)
            v += __shfl_down_sync(0xffffffffu, v, off);
        if ((c & 31) == 0) sred[c >> 5] = v;
        __syncthreads();
        if (c == 0) {
            float s = 0.f;
            #pragma unroll
            for (int w = 0; w < 16; ++w) s += sred[w];
            out[0] = 1.0f - s * (1.0f / 12582912.0f);
            g_count = 0;                   // re-arm for next graph replay
        }
    }
}

extern "C" void kernel_launch(void* const* d_in, const int* in_sizes, int n_in,
                              void* d_out, int out_size)
{
    (void)in_sizes; (void)n_in; (void)out_size;
    const float* pred = (const float*)d_in[0];
    const float* gt   = (const float*)d_in[1];

    dim3 grid(NSTRIP, N_IMG);              // (6, 48) = 288 blocks, 2 waves
    ssim_main<<<grid, IMG_W>>>(pred, gt, (float*)d_out);
}